// round 11
// baseline (speedup 1.0000x reference)
#include <cuda_runtime.h>
#include <math.h>
#include <stdint.h>

#define NT 365
#define NS 2048
#define NH 64
#define NG 128
#define NW 513   // NH*8+1
#define NS64 (NS * 64)

#define GEMM_BLOCKS 512                       // (NS/32) * 8 j-tiles
#define PART_BLOCKS ((NT * NS + 255) / 256)   // 2920

// ---------------- scratch (static device globals; no allocation) -------------
__device__ float4 g_flux[(NT + 8) * NS];   // [t][s] = {ps, pl, e, relu(Ta)}
__device__ float  g_w[(size_t)NS * 512];   // fc output w[s][j], j in [0,512)
__device__ float  g_par[11 * NS64];        // [p][s][h] folded params (scalar)
__device__ float  g_vi[NS];
__device__ float  g_qb[NS];

// param slots (folded)
#define P_GM    0   // exp(w)+1
#define P_NGE   1   // -2*sigmoid(w_ge)
#define P_GL    2   // exp(w_gl)
#define P_NGL   3   // -gl
#define P_K0M   4   // 1-k0
#define P_K0GA  5   // k0*ga
#define P_NK1   6   // -k1
#define P_KD    7   // k1*kb*(1-k2)
#define P_KQ1C  8   // k1*(1-kb)*ga + k1*kb*k2*ga
#define P_K2M   9   // 1-k2
#define P_K2GA 10   // k2*ga

__device__ __forceinline__ float sigmoidf_(float x) {
    return 1.0f / (1.0f + expf(-x));
}

// ---------------- kernel A: fused rain/snow partition + GEMM ------------------
__global__ void __launch_bounds__(256) k_pre(const float4* __restrict__ x,
                                             const float* __restrict__ xc,
                                             const float4* __restrict__ W4,
                                             const float* __restrict__ b) {
    __shared__ float xs[32 * 132];
    int tid = threadIdx.x;

    if (blockIdx.x < GEMM_BLOCKS) {
        int s0 = (blockIdx.x & 63) << 5;
        int jbase = (blockIdx.x >> 6) << 6;

        for (int idx = tid; idx < 32 * NG; idx += 256) {
            int sl = idx >> 7, c = idx & (NG - 1);
            xs[sl * 132 + c] = xc[(size_t)(s0 + sl) * NG + c];
        }
        __syncthreads();

        int sl = tid & 31;
        int joff = tid >> 5;
        float acc[8] = {0.f, 0.f, 0.f, 0.f, 0.f, 0.f, 0.f, 0.f};
        const float4* wrow[8];
#pragma unroll
        for (int i = 0; i < 8; i++)
            wrow[i] = W4 + (size_t)(jbase + joff + i * 8) * (NG / 4);
        const float4* xv4 = (const float4*)&xs[sl * 132];

#pragma unroll 4
        for (int c4 = 0; c4 < NG / 4; ++c4) {
            float4 xv = xv4[c4];
#pragma unroll
            for (int i = 0; i < 8; i++) {
                float4 wv = wrow[i][c4];
                acc[i] += xv.x * wv.x + xv.y * wv.y + xv.z * wv.z + xv.w * wv.w;
            }
        }
#pragma unroll
        for (int i = 0; i < 8; i++) {
            int j = jbase + joff + i * 8;
            g_w[(size_t)(s0 + sl) * 512 + j] = acc[i] + b[j];
        }
    } else {
        int i = (blockIdx.x - GEMM_BLOCKS) * 256 + tid;
        if (i >= NT * NS) return;
        float4 v = x[i];
        float P = v.x, E = v.y, T1 = v.z, T2 = v.w;
        float Ta = 0.5f * (T1 + T2);
        float rP;
        if (T1 >= 0.0f)      rP = 1.0f;
        else if (T2 <= 0.0f) rP = 0.0f;
        else                 rP = 1.0f - acosf((T1 + T2) / (T2 - T1)) / 3.1415f;
        float pl = rP * P;
        float ps = (1.0f - rP) * P;
        g_flux[i] = make_float4(ps, pl, E, fmaxf(Ta, 0.0f));
    }
}

// ---------------- kernel B: activations + folded params -----------------------
__global__ void __launch_bounds__(64) k_params(const float* __restrict__ xc,
                                               const float* __restrict__ W,
                                               const float* __restrict__ b) {
    int wid = (blockIdx.x * blockDim.x + threadIdx.x) >> 5;
    int lane = threadIdx.x & 31;
    if (wid >= NS) return;
    int s = wid;
    const float* wr = g_w + (size_t)s * 512;

    // cooperative dot for w[s][512]
    float p = 0.f;
    const float* w512row = W + 512 * NG;
    const float* xcr = xc + (size_t)s * NG;
#pragma unroll
    for (int k = 0; k < 4; k++)
        p = fmaf(xcr[lane + 32 * k], w512row[lane + 32 * k], p);
#pragma unroll
    for (int o = 16; o; o >>= 1) p += __shfl_xor_sync(0xffffffffu, p, o);
    float w512 = p + b[512];
    if (lane == 0) {
        g_vi[s] = sigmoidf_(w512);
        g_qb[s] = fmaxf(w512, 0.f) / (float)NH;
    }

    int hA = lane, hB = lane + 32;
    float wgmA = wr[0 * NH + hA], wgmB = wr[0 * NH + hB];
    float wgeA = wr[1 * NH + hA], wgeB = wr[1 * NH + hB];
    float wk0A = wr[3 * NH + hA], wk0B = wr[3 * NH + hB];
    float wk1A = wr[4 * NH + hA], wk1B = wr[4 * NH + hB];
    float wk2A = wr[5 * NH + hA], wk2B = wr[5 * NH + hB];
    float wglA = wr[6 * NH + hA], wglB = wr[6 * NH + hB];
    float wkbA = wr[7 * NH + hA], wkbB = wr[7 * NH + hB];

    // softmax over the k1 pre-activation slice (64 values across the warp)
    float m = fmaxf(wk1A, wk1B);
#pragma unroll
    for (int o = 16; o; o >>= 1) m = fmaxf(m, __shfl_xor_sync(0xffffffffu, m, o));
    float eA = expf(wk1A - m), eB = expf(wk1B - m);
    float sum = eA + eB;
#pragma unroll
    for (int o = 16; o; o >>= 1) sum += __shfl_xor_sync(0xffffffffu, sum, o);
    float inv = 1.0f / sum;
    float gaA = eA * inv, gaB = eB * inv;

    float glA = expf(wglA),               glB = expf(wglB);
    float k0A = sigmoidf_(wk0A),          k0B = sigmoidf_(wk0B);
    float k1A = sigmoidf_(wk1A),          k1B = sigmoidf_(wk1B);
    float k2A = sigmoidf_(wk2A),          k2B = sigmoidf_(wk2B);
    float kbA = sigmoidf_(wkbA) / 10.0f,  kbB = sigmoidf_(wkbB) / 10.0f;
    float kkbA = k1A * kbA,               kkbB = k1B * kbB;
    float k2mA = 1.0f - k2A,              k2mB = 1.0f - k2B;
    float k2gaA = k2A * gaA,              k2gaB = k2B * gaB;

    int base = s * 64 + lane;
#define ST(pidx, vA, vB) { g_par[(pidx) * NS64 + base] = (vA); \
                           g_par[(pidx) * NS64 + base + 32] = (vB); }
    ST(P_GM,    expf(wgmA) + 1.0f,        expf(wgmB) + 1.0f);
    ST(P_NGE,   -2.0f * sigmoidf_(wgeA),  -2.0f * sigmoidf_(wgeB));
    ST(P_GL,    glA,                      glB);
    ST(P_NGL,   -glA,                     -glB);
    ST(P_K0M,   1.0f - k0A,               1.0f - k0B);
    ST(P_K0GA,  k0A * gaA,                k0B * gaB);
    ST(P_NK1,   -k1A,                     -k1B);
    ST(P_KD,    kkbA * k2mA,              kkbB * k2mB);
    ST(P_KQ1C,  k1A * (1.0f - kbA) * gaA + kkbA * k2gaA,
                k1B * (1.0f - kbB) * gaB + kkbB * k2gaB);
    ST(P_K2M,   k2mA,                     k2mB);
    ST(P_K2GA,  k2gaA,                    k2gaB);
#undef ST
}

// ---------------- kernel C: sequential scan -----------------------------------
// 2 warps per site (4096 warps total); warp q of site s handles h = q*32+lane,
// ONE scalar chain per lane. Per-warp select-transpose reduction (deferred,
// pipelined over the 4-step unroll); the two half-warp partials combine via
// smem double-buffer + one __syncthreads per block; warp 0 stores (+qb).
__global__ void __launch_bounds__(64) k_scan(float* __restrict__ out) {
    int lane = threadIdx.x & 31;
    int q    = threadIdx.x >> 5;      // half: 0 or 1
    int l3   = lane & 3;
    int s    = blockIdx.x;
    int hb   = s * 64 + q * 32 + lane;

    float gm   = g_par[P_GM   * NS64 + hb];
    float nge  = g_par[P_NGE  * NS64 + hb];
    float gl   = g_par[P_GL   * NS64 + hb];
    float ngl  = g_par[P_NGL  * NS64 + hb];
    float k0m  = g_par[P_K0M  * NS64 + hb];
    float k0ga = g_par[P_K0GA * NS64 + hb];
    float nk1  = g_par[P_NK1  * NS64 + hb];
    float kd   = g_par[P_KD   * NS64 + hb];
    float kq1c = g_par[P_KQ1C * NS64 + hb];
    float k2m  = g_par[P_K2M  * NS64 + hb];
    float k2ga = g_par[P_K2GA * NS64 + hb];
    float vi = g_vi[s];
    float qb = g_qb[s];

    __shared__ float sbuf[2][4];

    float S0 = 0.f, H0 = ngl, H1 = 0.f, H2 = 0.f;
    float yv[4], ry[4], rv;

#define STEP(F, K)                                                             \
    {                                                                          \
        float ps = F.x, pl = F.y, e = F.z, tap = F.w;                          \
        float plvi = pl * vi;                                                  \
        float plv1 = pl - plvi;                                                \
        float am = tap * gm;                                                   \
        float Sm = fminf(S0, am);                                              \
        S0 = (S0 - Sm) + ps;                                                   \
        float G1 = fmaxf((H1 + Sm) + fmaf(e, nge, plvi), 0.f);                 \
        float G0 = fmaxf((H0 + G1) + plv1, 0.f);                               \
        H0 = fmaf(G0, k0m, ngl);                                               \
        float y = G0 * k0ga;                                                   \
        float m1 = fminf(G1, gl);                                              \
        H1 = fminf(fmaf(m1, nk1, G1), gl);                                     \
        y = fmaf(H2, k2ga, y);                                                 \
        y = fmaf(m1, kq1c, y);                                                 \
        float h2t = H2 * k2m;                                                  \
        H2 = fmaf(m1, kd, h2t);                                                \
        yv[K] = y;                                                             \
    }

#define RSTAGE4(o)                                                             \
    {                                                                          \
        float u0 = __shfl_xor_sync(0xffffffffu, ry[0], (o));                   \
        float u1 = __shfl_xor_sync(0xffffffffu, ry[1], (o));                   \
        float u2 = __shfl_xor_sync(0xffffffffu, ry[2], (o));                   \
        float u3 = __shfl_xor_sync(0xffffffffu, ry[3], (o));                   \
        ry[0] += u0; ry[1] += u1; ry[2] += u2; ry[3] += u3;                    \
    }
#define RSEL()                                                                 \
    {                                                                          \
        float rw;                                                              \
        rv = (l3 & 1) ? ry[1] : ry[0];                                         \
        rw = (l3 & 1) ? ry[3] : ry[2];                                         \
        rv = (l3 & 2) ? rw : rv;                                               \
    }
#define RSTAGE1(o) rv += __shfl_xor_sync(0xffffffffu, rv, (o));

    // combine half-warp partials via smem double-buffer; one sync per block
#define RCOMBINE(T, B)                                                         \
    {                                                                          \
        if (q && lane < 4) sbuf[B][lane] = rv;                                 \
        __syncthreads();                                                       \
        if (!q && lane < 4)                                                    \
            out[(size_t)((T) + lane) * NS + s] = (rv + sbuf[B][lane]) + qb;    \
    }

    // preload flux for block 0 (t = 0..3)
    float4 fc0 = g_flux[0 * NS + s];
    float4 fc1 = g_flux[1 * NS + s];
    float4 fc2 = g_flux[2 * NS + s];
    float4 fc3 = g_flux[3 * NS + s];

    // block 0: compute only (its reduction happens inside iteration tb=1)
    {
        float4 fn0 = g_flux[(size_t)4 * NS + s];
        float4 fn1 = g_flux[(size_t)5 * NS + s];
        float4 fn2 = g_flux[(size_t)6 * NS + s];
        float4 fn3 = g_flux[(size_t)7 * NS + s];
        STEP(fc0, 0)
        STEP(fc1, 1)
        STEP(fc2, 2)
        STEP(fc3, 3)
        ry[0] = yv[0]; ry[1] = yv[1]; ry[2] = yv[2]; ry[3] = yv[3];
        fc0 = fn0; fc1 = fn1; fc2 = fn2; fc3 = fn3;
    }

    // main loop: blocks 1..90 (t = 4..363), reduce block tb-1 interleaved
    for (int tb = 1; tb < 91; ++tb) {
        int t = tb * 4;
        float4 fn0 = g_flux[(size_t)(t + 4) * NS + s];
        float4 fn1 = g_flux[(size_t)(t + 5) * NS + s];
        float4 fn2 = g_flux[(size_t)(t + 6) * NS + s];
        float4 fn3 = g_flux[(size_t)(t + 7) * NS + s];

        STEP(fc0, 0)
        RSTAGE4(1)
        STEP(fc1, 1)
        RSTAGE4(2)
        STEP(fc2, 2)
        RSEL()
        RSTAGE1(4)
        STEP(fc3, 3)
        RSTAGE1(8)
        RSTAGE1(16)
        RCOMBINE(t - 4, (tb - 1) & 1)

        ry[0] = yv[0]; ry[1] = yv[1]; ry[2] = yv[2]; ry[3] = yv[3];
        fc0 = fn0; fc1 = fn1; fc2 = fn2; fc3 = fn3;
    }

    // drain block 90 reduction (t = 360..363)
    RSTAGE4(1) RSTAGE4(2) RSEL() RSTAGE1(4) RSTAGE1(8) RSTAGE1(16)
    RCOMBINE(360, 0)

    // epilogue: t = 364 (fc0 holds flux row 364 after last rotate)
    STEP(fc0, 0)
    rv = yv[0];
#pragma unroll
    for (int o = 16; o; o >>= 1) rv += __shfl_xor_sync(0xffffffffu, rv, o);
    {
        if (q && lane == 0) sbuf[1][0] = rv;
        __syncthreads();
        if (!q && lane == 0) out[(size_t)364 * NS + s] = (rv + sbuf[1][0]) + qb;
    }
#undef STEP
#undef RSTAGE4
#undef RSEL
#undef RSTAGE1
#undef RCOMBINE
}

// ---------------- launch ------------------------------------------------------
extern "C" void kernel_launch(void* const* d_in, const int* in_sizes, int n_in,
                              void* d_out, int out_size) {
    const float* x  = (const float*)d_in[0];  // [NT, NS, 4]
    const float* xc = (const float*)d_in[1];  // [NS, NG]
    const float* W  = (const float*)d_in[2];  // [NW, NG]
    const float* b  = (const float*)d_in[3];  // [NW]
    float* out = (float*)d_out;               // [NT, NS]

    k_pre<<<GEMM_BLOCKS + PART_BLOCKS, 256>>>((const float4*)x, xc,
                                              (const float4*)W, b);
    k_params<<<NS / 2, 64>>>(xc, W, b);
    k_scan<<<NS, 64>>>(out);   // 2048 blocks; 2 half-warps per site
}

// round 12
// speedup vs baseline: 1.3382x; 1.3382x over previous
#include <cuda_runtime.h>
#include <math.h>
#include <stdint.h>

#define NT 365
#define NS 2048
#define NH 64
#define NG 128
#define NW 513   // NH*8+1

// ---------------- scratch (static device globals; no allocation) -------------
__device__ float4 g_flux[(NT + 8) * NS];   // [t][s] = {ps, pl, e, relu(Ta)}
__device__ float  g_w[(size_t)NS * 512];   // fc output w[s][j], j in [0,512)
__device__ float2 g_par2[11 * NS * 32];    // [p][s][j] = {val(h=j), val(h=j+32)}
__device__ float  g_vi[NS];
__device__ float  g_qb[NS];

// param slots (folded)
#define P_GM    0   // exp(w)+1
#define P_NGE   1   // -2*sigmoid(w_ge)
#define P_GL    2   // exp(w_gl)
#define P_NGL   3   // -gl
#define P_K0M   4   // 1-k0
#define P_K0GA  5   // k0*ga
#define P_NK1   6   // -k1
#define P_KD    7   // k1*kb*(1-k2)
#define P_KQ1C  8   // k1*(1-kb)*ga + k1*kb*k2*ga
#define P_K2M   9   // 1-k2
#define P_K2GA 10   // k2*ga

__device__ __forceinline__ float sigmoidf_(float x) {
    return 1.0f / (1.0f + expf(-x));
}

// ---------------- kernel A: rain/snow partition -------------------------------
__global__ void k_part(const float4* __restrict__ x) {
    int i = blockIdx.x * blockDim.x + threadIdx.x;
    if (i >= NT * NS) return;
    float4 v = x[i];
    float P = v.x, E = v.y, T1 = v.z, T2 = v.w;
    float Ta = 0.5f * (T1 + T2);
    float rP;
    if (T1 >= 0.0f)      rP = 1.0f;
    else if (T2 <= 0.0f) rP = 0.0f;
    else                 rP = 1.0f - acosf((T1 + T2) / (T2 - T1)) / 3.1415f;
    float pl = rP * P;
    float ps = (1.0f - rP) * P;
    g_flux[i] = make_float4(ps, pl, E, fmaxf(Ta, 0.0f));
}

// ---------------- kernel B: w = xc @ W^T + b (both operands in smem) ----------
// grid (64, 16): 32-site x 32-j tile per block, 256 threads.
// W tile staged in shared (coalesced) -> inner loop is LDS-broadcast + FFMA.
__global__ void __launch_bounds__(256) k_gemm(const float* __restrict__ xc,
                                              const float* __restrict__ W,
                                              const float* __restrict__ b) {
    __shared__ float xs[32 * 132];   // [site][c], padded stride
    __shared__ float ws[32 * 128];   // [j_local][c]
    int tid = threadIdx.x;
    int s0 = blockIdx.x << 5;
    int jbase = blockIdx.y << 5;

    // load xc tile (32 x 128), coalesced
    for (int idx = tid; idx < 32 * NG; idx += 256) {
        int sl = idx >> 7, c = idx & (NG - 1);
        xs[sl * 132 + c] = xc[(size_t)(s0 + sl) * NG + c];
    }
    // load W tile (32 x 128), coalesced float4
    {
        const float4* Wt = (const float4*)(W + (size_t)jbase * NG);
        float4* ws4 = (float4*)ws;
        for (int idx = tid; idx < 32 * NG / 4; idx += 256)
            ws4[idx] = Wt[idx];
    }
    __syncthreads();

    int sl = tid & 31;      // site within tile
    int joff = tid >> 5;    // 0..7; this thread does j_local = joff + {0,8,16,24}
    float acc[4] = {0.f, 0.f, 0.f, 0.f};
    const float4* xv4 = (const float4*)&xs[sl * 132];
    const float4* wr0 = (const float4*)&ws[(joff +  0) * NG];
    const float4* wr1 = (const float4*)&ws[(joff +  8) * NG];
    const float4* wr2 = (const float4*)&ws[(joff + 16) * NG];
    const float4* wr3 = (const float4*)&ws[(joff + 24) * NG];

#pragma unroll 8
    for (int c4 = 0; c4 < NG / 4; ++c4) {
        float4 xv = xv4[c4];
        float4 w0 = wr0[c4], w1 = wr1[c4], w2 = wr2[c4], w3 = wr3[c4];
        acc[0] += xv.x * w0.x + xv.y * w0.y + xv.z * w0.z + xv.w * w0.w;
        acc[1] += xv.x * w1.x + xv.y * w1.y + xv.z * w1.z + xv.w * w1.w;
        acc[2] += xv.x * w2.x + xv.y * w2.y + xv.z * w2.z + xv.w * w2.w;
        acc[3] += xv.x * w3.x + xv.y * w3.y + xv.z * w3.z + xv.w * w3.w;
    }
#pragma unroll
    for (int i = 0; i < 4; i++) {
        int j = jbase + joff + i * 8;
        g_w[(size_t)(s0 + sl) * 512 + j] = acc[i] + b[j];
    }
}

// ---------------- kernel C: activations + folded params (R8) ------------------
__global__ void __launch_bounds__(64) k_params(const float* __restrict__ xc,
                                               const float* __restrict__ W,
                                               const float* __restrict__ b) {
    int wid = (blockIdx.x * blockDim.x + threadIdx.x) >> 5;
    int lane = threadIdx.x & 31;
    if (wid >= NS) return;
    int s = wid;
    const float* wr = g_w + (size_t)s * 512;

    // cooperative dot for w[s][512]
    float p = 0.f;
    const float* w512row = W + 512 * NG;
    const float* xcr = xc + (size_t)s * NG;
#pragma unroll
    for (int k = 0; k < 4; k++)
        p = fmaf(xcr[lane + 32 * k], w512row[lane + 32 * k], p);
#pragma unroll
    for (int o = 16; o; o >>= 1) p += __shfl_xor_sync(0xffffffffu, p, o);
    float w512 = p + b[512];
    if (lane == 0) {
        g_vi[s] = sigmoidf_(w512);
        g_qb[s] = fmaxf(w512, 0.f) / (float)NH;
    }

    int hA = lane, hB = lane + 32;
    float wgmA = wr[0 * NH + hA], wgmB = wr[0 * NH + hB];
    float wgeA = wr[1 * NH + hA], wgeB = wr[1 * NH + hB];
    float wk0A = wr[3 * NH + hA], wk0B = wr[3 * NH + hB];
    float wk1A = wr[4 * NH + hA], wk1B = wr[4 * NH + hB];
    float wk2A = wr[5 * NH + hA], wk2B = wr[5 * NH + hB];
    float wglA = wr[6 * NH + hA], wglB = wr[6 * NH + hB];
    float wkbA = wr[7 * NH + hA], wkbB = wr[7 * NH + hB];

    // softmax over the k1 pre-activation slice (64 values across the warp)
    float m = fmaxf(wk1A, wk1B);
#pragma unroll
    for (int o = 16; o; o >>= 1) m = fmaxf(m, __shfl_xor_sync(0xffffffffu, m, o));
    float eA = expf(wk1A - m), eB = expf(wk1B - m);
    float sum = eA + eB;
#pragma unroll
    for (int o = 16; o; o >>= 1) sum += __shfl_xor_sync(0xffffffffu, sum, o);
    float inv = 1.0f / sum;
    float gaA = eA * inv, gaB = eB * inv;

    float glA = expf(wglA),               glB = expf(wglB);
    float k0A = sigmoidf_(wk0A),          k0B = sigmoidf_(wk0B);
    float k1A = sigmoidf_(wk1A),          k1B = sigmoidf_(wk1B);
    float k2A = sigmoidf_(wk2A),          k2B = sigmoidf_(wk2B);
    float kbA = sigmoidf_(wkbA) / 10.0f,  kbB = sigmoidf_(wkbB) / 10.0f;
    float kkbA = k1A * kbA,               kkbB = k1B * kbB;
    float k2mA = 1.0f - k2A,              k2mB = 1.0f - k2B;
    float k2gaA = k2A * gaA,              k2gaB = k2B * gaB;

    int pb = s * 32 + lane;
#define ST(pidx, vA, vB) g_par2[(pidx) * (NS * 32) + pb] = make_float2((vA), (vB));
    ST(P_GM,    expf(wgmA) + 1.0f,        expf(wgmB) + 1.0f);
    ST(P_NGE,   -2.0f * sigmoidf_(wgeA),  -2.0f * sigmoidf_(wgeB));
    ST(P_GL,    glA,                      glB);
    ST(P_NGL,   -glA,                     -glB);
    ST(P_K0M,   1.0f - k0A,               1.0f - k0B);
    ST(P_K0GA,  k0A * gaA,                k0B * gaB);
    ST(P_NK1,   -k1A,                     -k1B);
    ST(P_KD,    kkbA * k2mA,              kkbB * k2mB);
    ST(P_KQ1C,  k1A * (1.0f - kbA) * gaA + kkbA * k2gaA,
                k1B * (1.0f - kbB) * gaB + kkbB * k2gaB);
    ST(P_K2M,   k2mA,                     k2mB);
    ST(P_K2GA,  k2gaA,                    k2gaB);
#undef ST
}

// ---------------- kernel D: sequential scan (R8 configuration) ----------------
// 1 warp per site (2048 warps); each lane carries TWO independent scalar
// chains (h = lane, h = lane+32). Reduction of block i is software-pipelined
// into block i+1 via select-transpose; lanes 0..3 store.
__global__ void __launch_bounds__(64) k_scan(float* __restrict__ out) {
    int lane = threadIdx.x & 31;
    int l3 = lane & 3;
    int s = blockIdx.x * 2 + (threadIdx.x >> 5);
    int pb = s * 32 + lane;

#define LDP(p) g_par2[(p) * (NS * 32) + pb]
    float2 gm    = LDP(P_GM);
    float2 nge   = LDP(P_NGE);
    float2 gl    = LDP(P_GL);
    float2 ngl   = LDP(P_NGL);
    float2 k0m   = LDP(P_K0M);
    float2 k0ga  = LDP(P_K0GA);
    float2 nk1   = LDP(P_NK1);
    float2 kd    = LDP(P_KD);
    float2 kq1c  = LDP(P_KQ1C);
    float2 k2m   = LDP(P_K2M);
    float2 k2ga  = LDP(P_K2GA);
#undef LDP
    float vi = g_vi[s];
    float qb = g_qb[s];

    float S0A = 0.f, H0A = ngl.x, H1A = 0.f, H2A = 0.f;
    float S0B = 0.f, H0B = ngl.y, H1B = 0.f, H2B = 0.f;
    float yv[4], ry[4], rv;

#define STEP(F, K)                                                             \
    {                                                                          \
        float ps = F.x, pl = F.y, e = F.z, tap = F.w;                          \
        float plvi = pl * vi;                                                  \
        float plv1 = pl - plvi;                                                \
        /* chain A (h = lane) */                                               \
        float amA = tap * gm.x;                                                \
        float SmA = fminf(S0A, amA);                                           \
        S0A = (S0A - SmA) + ps;                                                \
        float G1A = fmaxf((H1A + SmA) + fmaf(e, nge.x, plvi), 0.f);            \
        float G0A = fmaxf((H0A + G1A) + plv1, 0.f);                            \
        H0A = fmaf(G0A, k0m.x, ngl.x);                                         \
        float yA = G0A * k0ga.x;                                               \
        float m1A = fminf(G1A, gl.x);                                          \
        H1A = fminf(fmaf(m1A, nk1.x, G1A), gl.x);                              \
        yA = fmaf(H2A, k2ga.x, yA);                                            \
        yA = fmaf(m1A, kq1c.x, yA);                                            \
        float h2tA = H2A * k2m.x;                                              \
        H2A = fmaf(m1A, kd.x, h2tA);                                           \
        /* chain B (h = lane+32) */                                            \
        float amB = tap * gm.y;                                                \
        float SmB = fminf(S0B, amB);                                           \
        S0B = (S0B - SmB) + ps;                                                \
        float G1B = fmaxf((H1B + SmB) + fmaf(e, nge.y, plvi), 0.f);            \
        float G0B = fmaxf((H0B + G1B) + plv1, 0.f);                            \
        H0B = fmaf(G0B, k0m.y, ngl.y);                                         \
        float yB = G0B * k0ga.y;                                               \
        float m1B = fminf(G1B, gl.y);                                          \
        H1B = fminf(fmaf(m1B, nk1.y, G1B), gl.y);                              \
        yB = fmaf(H2B, k2ga.y, yB);                                            \
        yB = fmaf(m1B, kq1c.y, yB);                                            \
        float h2tB = H2B * k2m.y;                                              \
        H2B = fmaf(m1B, kd.y, h2tB);                                           \
        yv[K] = yA + yB;                                                       \
    }

#define RSTAGE4(o)                                                             \
    {                                                                          \
        float u0 = __shfl_xor_sync(0xffffffffu, ry[0], (o));                   \
        float u1 = __shfl_xor_sync(0xffffffffu, ry[1], (o));                   \
        float u2 = __shfl_xor_sync(0xffffffffu, ry[2], (o));                   \
        float u3 = __shfl_xor_sync(0xffffffffu, ry[3], (o));                   \
        ry[0] += u0; ry[1] += u1; ry[2] += u2; ry[3] += u3;                    \
    }
#define RSEL()                                                                 \
    {                                                                          \
        float rw;                                                              \
        rv = (l3 & 1) ? ry[1] : ry[0];                                         \
        rw = (l3 & 1) ? ry[3] : ry[2];                                         \
        rv = (l3 & 2) ? rw : rv;                                               \
    }
#define RSTAGE1(o) rv += __shfl_xor_sync(0xffffffffu, rv, (o));
#define RSTORE(T)                                                              \
    if (lane < 4) out[(size_t)((T) + lane) * NS + s] = rv + qb;

    // preload flux for block 0 (t = 0..3)
    float4 fc0 = g_flux[0 * NS + s];
    float4 fc1 = g_flux[1 * NS + s];
    float4 fc2 = g_flux[2 * NS + s];
    float4 fc3 = g_flux[3 * NS + s];

    // block 0: compute only (its reduction happens inside iteration tb=1)
    {
        float4 fn0 = g_flux[(size_t)4 * NS + s];
        float4 fn1 = g_flux[(size_t)5 * NS + s];
        float4 fn2 = g_flux[(size_t)6 * NS + s];
        float4 fn3 = g_flux[(size_t)7 * NS + s];
        STEP(fc0, 0)
        STEP(fc1, 1)
        STEP(fc2, 2)
        STEP(fc3, 3)
        ry[0] = yv[0]; ry[1] = yv[1]; ry[2] = yv[2]; ry[3] = yv[3];
        fc0 = fn0; fc1 = fn1; fc2 = fn2; fc3 = fn3;
    }

    // main loop: blocks 1..90 (t = 4..363), reduce block tb-1 interleaved
    for (int tb = 1; tb < 91; ++tb) {
        int t = tb * 4;
        float4 fn0 = g_flux[(size_t)(t + 4) * NS + s];
        float4 fn1 = g_flux[(size_t)(t + 5) * NS + s];
        float4 fn2 = g_flux[(size_t)(t + 6) * NS + s];
        float4 fn3 = g_flux[(size_t)(t + 7) * NS + s];

        STEP(fc0, 0)
        RSTAGE4(1)
        STEP(fc1, 1)
        RSTAGE4(2)
        STEP(fc2, 2)
        RSEL()
        RSTAGE1(4)
        STEP(fc3, 3)
        RSTAGE1(8)
        RSTAGE1(16)
        RSTORE(t - 4)

        ry[0] = yv[0]; ry[1] = yv[1]; ry[2] = yv[2]; ry[3] = yv[3];
        fc0 = fn0; fc1 = fn1; fc2 = fn2; fc3 = fn3;
    }

    // drain block 90 reduction (t = 360..363)
    RSTAGE4(1) RSTAGE4(2) RSEL() RSTAGE1(4) RSTAGE1(8) RSTAGE1(16)
    RSTORE(360)

    // epilogue: t = 364 (fc0 holds flux row 364 after last rotate)
    STEP(fc0, 0)
    rv = yv[0];
#pragma unroll
    for (int o = 16; o; o >>= 1) rv += __shfl_xor_sync(0xffffffffu, rv, o);
    if (lane == 0) out[(size_t)364 * NS + s] = rv + qb;
#undef STEP
#undef RSTAGE4
#undef RSEL
#undef RSTAGE1
#undef RSTORE
}

// ---------------- launch ------------------------------------------------------
extern "C" void kernel_launch(void* const* d_in, const int* in_sizes, int n_in,
                              void* d_out, int out_size) {
    const float* x  = (const float*)d_in[0];  // [NT, NS, 4]
    const float* xc = (const float*)d_in[1];  // [NS, NG]
    const float* W  = (const float*)d_in[2];  // [NW, NG]
    const float* b  = (const float*)d_in[3];  // [NW]
    float* out = (float*)d_out;               // [NT, NS]

    k_part<<<(NT * NS + 255) / 256, 256>>>((const float4*)x);
    dim3 gB(NS / 32, 16);
    k_gemm<<<gB, 256>>>(xc, W, b);
    k_params<<<NS / 2, 64>>>(xc, W, b);
    k_scan<<<NS / 2, 64>>>(out);
}

// round 13
// speedup vs baseline: 1.3901x; 1.0388x over previous
#include <cuda_runtime.h>
#include <math.h>
#include <stdint.h>

#define NT 365
#define NS 2048
#define NH 64
#define NG 128
#define NW 513   // NH*8+1

#define GEMM_BLOCKS 1024                      // 64 site-tiles x 16 j-tiles
#define PART_BLOCKS ((NT * NS + 255) / 256)   // 2920

// ---------------- scratch (static device globals; no allocation) -------------
__device__ float4 g_flux[(NT + 8) * NS];   // [t][s] = {ps, pl, e, relu(Ta)}
__device__ float  g_w[(size_t)NS * 512];   // fc output w[s][j], j in [0,512)

__device__ __forceinline__ float sigmoidf_(float x) {
    return 1.0f / (1.0f + expf(-x));
}

// ---------------- kernel A: fused rain/snow partition + GEMM ------------------
// blockIdx.x <  GEMM_BLOCKS : 32-site x 32-j GEMM tile (both operands in smem)
// blockIdx.x >= GEMM_BLOCKS : 256-element partition chunk
__global__ void __launch_bounds__(256) k_pre(const float4* __restrict__ x,
                                             const float* __restrict__ xc,
                                             const float* __restrict__ W,
                                             const float* __restrict__ b) {
    __shared__ float xs[32 * 132];   // [site][c], padded stride
    __shared__ float ws[32 * 128];   // [j_local][c]
    int tid = threadIdx.x;

    if (blockIdx.x < GEMM_BLOCKS) {
        int s0 = (blockIdx.x & 63) << 5;      // 64 site-tiles
        int jbase = (blockIdx.x >> 6) << 5;   // 16 j-tiles

        // load xc tile (32 x 128), coalesced
        for (int idx = tid; idx < 32 * NG; idx += 256) {
            int sl = idx >> 7, c = idx & (NG - 1);
            xs[sl * 132 + c] = xc[(size_t)(s0 + sl) * NG + c];
        }
        // load W tile (32 x 128), coalesced float4
        {
            const float4* Wt = (const float4*)(W + (size_t)jbase * NG);
            float4* ws4 = (float4*)ws;
            for (int idx = tid; idx < 32 * NG / 4; idx += 256)
                ws4[idx] = Wt[idx];
        }
        __syncthreads();

        int sl = tid & 31;      // site within tile
        int joff = tid >> 5;    // 0..7; j_local = joff + {0,8,16,24}
        float acc[4] = {0.f, 0.f, 0.f, 0.f};
        const float4* xv4 = (const float4*)&xs[sl * 132];
        const float4* wr0 = (const float4*)&ws[(joff +  0) * NG];
        const float4* wr1 = (const float4*)&ws[(joff +  8) * NG];
        const float4* wr2 = (const float4*)&ws[(joff + 16) * NG];
        const float4* wr3 = (const float4*)&ws[(joff + 24) * NG];

#pragma unroll 8
        for (int c4 = 0; c4 < NG / 4; ++c4) {
            float4 xv = xv4[c4];
            float4 w0 = wr0[c4], w1 = wr1[c4], w2 = wr2[c4], w3 = wr3[c4];
            acc[0] += xv.x * w0.x + xv.y * w0.y + xv.z * w0.z + xv.w * w0.w;
            acc[1] += xv.x * w1.x + xv.y * w1.y + xv.z * w1.z + xv.w * w1.w;
            acc[2] += xv.x * w2.x + xv.y * w2.y + xv.z * w2.z + xv.w * w2.w;
            acc[3] += xv.x * w3.x + xv.y * w3.y + xv.z * w3.z + xv.w * w3.w;
        }
#pragma unroll
        for (int i = 0; i < 4; i++) {
            int j = jbase + joff + i * 8;
            g_w[(size_t)(s0 + sl) * 512 + j] = acc[i] + b[j];
        }
    } else {
        int i = (blockIdx.x - GEMM_BLOCKS) * 256 + tid;
        if (i >= NT * NS) return;
        float4 v = x[i];
        float P = v.x, E = v.y, T1 = v.z, T2 = v.w;
        float Ta = 0.5f * (T1 + T2);
        float rP;
        if (T1 >= 0.0f)      rP = 1.0f;
        else if (T2 <= 0.0f) rP = 0.0f;
        else                 rP = 1.0f - acosf((T1 + T2) / (T2 - T1)) / 3.1415f;
        float pl = rP * P;
        float ps = (1.0f - rP) * P;
        g_flux[i] = make_float4(ps, pl, E, fmaxf(Ta, 0.0f));
    }
}

// ---------------- kernel B: fused params + sequential scan --------------------
// 1 warp per site (2048 warps). Prologue: folded params computed in registers
// from the g_w row + the w512 dot. Main loop: each lane carries two
// independent scalar chains (h = lane, h = lane+32); reduction of block i is
// software-pipelined into block i+1 via select-transpose; lanes 0..3 store.
__global__ void __launch_bounds__(64) k_scan(float* __restrict__ out,
                                             const float* __restrict__ xc,
                                             const float* __restrict__ W,
                                             const float* __restrict__ b) {
    int lane = threadIdx.x & 31;
    int l3 = lane & 3;
    int s = blockIdx.x * 2 + (threadIdx.x >> 5);

    // ================= prologue: params in registers =================
    const float* wr = g_w + (size_t)s * 512;
    int hA = lane, hB = lane + 32;
    float wgmA = wr[0 * NH + hA], wgmB = wr[0 * NH + hB];
    float wgeA = wr[1 * NH + hA], wgeB = wr[1 * NH + hB];
    float wk0A = wr[3 * NH + hA], wk0B = wr[3 * NH + hB];
    float wk1A = wr[4 * NH + hA], wk1B = wr[4 * NH + hB];
    float wk2A = wr[5 * NH + hA], wk2B = wr[5 * NH + hB];
    float wglA = wr[6 * NH + hA], wglB = wr[6 * NH + hB];
    float wkbA = wr[7 * NH + hA], wkbB = wr[7 * NH + hB];

    // w512 = xc[s]·W[512] + b[512]
    float p = 0.f;
    const float* w512row = W + 512 * NG;
    const float* xcr = xc + (size_t)s * NG;
#pragma unroll
    for (int k = 0; k < 4; k++)
        p = fmaf(xcr[lane + 32 * k], w512row[lane + 32 * k], p);
#pragma unroll
    for (int o = 16; o; o >>= 1) p += __shfl_xor_sync(0xffffffffu, p, o);
    float w512 = p + b[512];
    float vi = sigmoidf_(w512);
    float qb = fmaxf(w512, 0.f) / (float)NH;

    // softmax over the k1 pre-activation slice (64 values across the warp)
    float mx = fmaxf(wk1A, wk1B);
#pragma unroll
    for (int o = 16; o; o >>= 1) mx = fmaxf(mx, __shfl_xor_sync(0xffffffffu, mx, o));
    float eA = expf(wk1A - mx), eB = expf(wk1B - mx);
    float sum = eA + eB;
#pragma unroll
    for (int o = 16; o; o >>= 1) sum += __shfl_xor_sync(0xffffffffu, sum, o);
    float inv = 1.0f / sum;
    float gaA = eA * inv, gaB = eB * inv;

    float k0A = sigmoidf_(wk0A),          k0B = sigmoidf_(wk0B);
    float k1A = sigmoidf_(wk1A),          k1B = sigmoidf_(wk1B);
    float k2A = sigmoidf_(wk2A),          k2B = sigmoidf_(wk2B);
    float kbA = sigmoidf_(wkbA) / 10.0f,  kbB = sigmoidf_(wkbB) / 10.0f;
    float kkbA = k1A * kbA,               kkbB = k1B * kbB;

    float2 gm    = make_float2(expf(wgmA) + 1.0f,       expf(wgmB) + 1.0f);
    float2 nge   = make_float2(-2.0f * sigmoidf_(wgeA), -2.0f * sigmoidf_(wgeB));
    float2 gl    = make_float2(expf(wglA),              expf(wglB));
    float2 ngl   = make_float2(-gl.x,                   -gl.y);
    float2 k0m   = make_float2(1.0f - k0A,              1.0f - k0B);
    float2 k0ga  = make_float2(k0A * gaA,               k0B * gaB);
    float2 nk1   = make_float2(-k1A,                    -k1B);
    float2 k2m   = make_float2(1.0f - k2A,              1.0f - k2B);
    float2 k2ga  = make_float2(k2A * gaA,               k2B * gaB);
    float2 kd    = make_float2(kkbA * k2m.x,            kkbB * k2m.y);
    float2 kq1c  = make_float2(k1A * (1.0f - kbA) * gaA + kkbA * k2ga.x,
                               k1B * (1.0f - kbB) * gaB + kkbB * k2ga.y);

    // ================= main loop =================
    float S0A = 0.f, H0A = ngl.x, H1A = 0.f, H2A = 0.f;
    float S0B = 0.f, H0B = ngl.y, H1B = 0.f, H2B = 0.f;
    float yv[4], ry[4], rv;

#define STEP(F, K)                                                             \
    {                                                                          \
        float ps = F.x, pl = F.y, e = F.z, tap = F.w;                          \
        float plvi = pl * vi;                                                  \
        float plv1 = pl - plvi;                                                \
        /* chain A (h = lane) */                                               \
        float amA = tap * gm.x;                                                \
        float SmA = fminf(S0A, amA);                                           \
        S0A = (S0A - SmA) + ps;                                                \
        float G1A = fmaxf((H1A + SmA) + fmaf(e, nge.x, plvi), 0.f);            \
        float G0A = fmaxf((H0A + G1A) + plv1, 0.f);                            \
        H0A = fmaf(G0A, k0m.x, ngl.x);                                         \
        float yA = G0A * k0ga.x;                                               \
        float m1A = fminf(G1A, gl.x);                                          \
        H1A = fminf(fmaf(m1A, nk1.x, G1A), gl.x);                              \
        yA = fmaf(H2A, k2ga.x, yA);                                            \
        yA = fmaf(m1A, kq1c.x, yA);                                            \
        float h2tA = H2A * k2m.x;                                              \
        H2A = fmaf(m1A, kd.x, h2tA);                                           \
        /* chain B (h = lane+32) */                                            \
        float amB = tap * gm.y;                                                \
        float SmB = fminf(S0B, amB);                                           \
        S0B = (S0B - SmB) + ps;                                                \
        float G1B = fmaxf((H1B + SmB) + fmaf(e, nge.y, plvi), 0.f);            \
        float G0B = fmaxf((H0B + G1B) + plv1, 0.f);                            \
        H0B = fmaf(G0B, k0m.y, ngl.y);                                         \
        float yB = G0B * k0ga.y;                                               \
        float m1B = fminf(G1B, gl.y);                                          \
        H1B = fminf(fmaf(m1B, nk1.y, G1B), gl.y);                              \
        yB = fmaf(H2B, k2ga.y, yB);                                            \
        yB = fmaf(m1B, kq1c.y, yB);                                            \
        float h2tB = H2B * k2m.y;                                              \
        H2B = fmaf(m1B, kd.y, h2tB);                                           \
        yv[K] = yA + yB;                                                       \
    }

#define RSTAGE4(o)                                                             \
    {                                                                          \
        float u0 = __shfl_xor_sync(0xffffffffu, ry[0], (o));                   \
        float u1 = __shfl_xor_sync(0xffffffffu, ry[1], (o));                   \
        float u2 = __shfl_xor_sync(0xffffffffu, ry[2], (o));                   \
        float u3 = __shfl_xor_sync(0xffffffffu, ry[3], (o));                   \
        ry[0] += u0; ry[1] += u1; ry[2] += u2; ry[3] += u3;                    \
    }
#define RSEL()                                                                 \
    {                                                                          \
        float rw;                                                              \
        rv = (l3 & 1) ? ry[1] : ry[0];                                         \
        rw = (l3 & 1) ? ry[3] : ry[2];                                         \
        rv = (l3 & 2) ? rw : rv;                                               \
    }
#define RSTAGE1(o) rv += __shfl_xor_sync(0xffffffffu, rv, (o));
#define RSTORE(T)                                                              \
    if (lane < 4) out[(size_t)((T) + lane) * NS + s] = rv + qb;

    // preload flux for block 0 (t = 0..3)
    float4 fc0 = g_flux[0 * NS + s];
    float4 fc1 = g_flux[1 * NS + s];
    float4 fc2 = g_flux[2 * NS + s];
    float4 fc3 = g_flux[3 * NS + s];

    // block 0: compute only (its reduction happens inside iteration tb=1)
    {
        float4 fn0 = g_flux[(size_t)4 * NS + s];
        float4 fn1 = g_flux[(size_t)5 * NS + s];
        float4 fn2 = g_flux[(size_t)6 * NS + s];
        float4 fn3 = g_flux[(size_t)7 * NS + s];
        STEP(fc0, 0)
        STEP(fc1, 1)
        STEP(fc2, 2)
        STEP(fc3, 3)
        ry[0] = yv[0]; ry[1] = yv[1]; ry[2] = yv[2]; ry[3] = yv[3];
        fc0 = fn0; fc1 = fn1; fc2 = fn2; fc3 = fn3;
    }

    // main loop: blocks 1..90 (t = 4..363), reduce block tb-1 interleaved
    for (int tb = 1; tb < 91; ++tb) {
        int t = tb * 4;
        float4 fn0 = g_flux[(size_t)(t + 4) * NS + s];
        float4 fn1 = g_flux[(size_t)(t + 5) * NS + s];
        float4 fn2 = g_flux[(size_t)(t + 6) * NS + s];
        float4 fn3 = g_flux[(size_t)(t + 7) * NS + s];

        STEP(fc0, 0)
        RSTAGE4(1)
        STEP(fc1, 1)
        RSTAGE4(2)
        STEP(fc2, 2)
        RSEL()
        RSTAGE1(4)
        STEP(fc3, 3)
        RSTAGE1(8)
        RSTAGE1(16)
        RSTORE(t - 4)

        ry[0] = yv[0]; ry[1] = yv[1]; ry[2] = yv[2]; ry[3] = yv[3];
        fc0 = fn0; fc1 = fn1; fc2 = fn2; fc3 = fn3;
    }

    // drain block 90 reduction (t = 360..363)
    RSTAGE4(1) RSTAGE4(2) RSEL() RSTAGE1(4) RSTAGE1(8) RSTAGE1(16)
    RSTORE(360)

    // epilogue: t = 364 (fc0 holds flux row 364 after last rotate)
    STEP(fc0, 0)
    rv = yv[0];
#pragma unroll
    for (int o = 16; o; o >>= 1) rv += __shfl_xor_sync(0xffffffffu, rv, o);
    if (lane == 0) out[(size_t)364 * NS + s] = rv + qb;
#undef STEP
#undef RSTAGE4
#undef RSEL
#undef RSTAGE1
#undef RSTORE
}

// ---------------- launch ------------------------------------------------------
extern "C" void kernel_launch(void* const* d_in, const int* in_sizes, int n_in,
                              void* d_out, int out_size) {
    const float* x  = (const float*)d_in[0];  // [NT, NS, 4]
    const float* xc = (const float*)d_in[1];  // [NS, NG]
    const float* W  = (const float*)d_in[2];  // [NW, NG]
    const float* b  = (const float*)d_in[3];  // [NW]
    float* out = (float*)d_out;               // [NT, NS]

    k_pre<<<GEMM_BLOCKS + PART_BLOCKS, 256>>>((const float4*)x, xc, W, b);
    k_scan<<<NS / 2, 64>>>(out, xc, W, b);   // fused params + scan
}